// round 1
// baseline (speedup 1.0000x reference)
#include <cuda_runtime.h>
#include <cuda_bf16.h>

#define CIN 64
#define COUT 64
#define NOFFS 26
#define NTAPS 27
#define WTILE (CIN * COUT)   // 4096 floats = 16 KB

// Transposed weights: wt[t][ci][co], t in 0..26 (tap index dz*9+dy*3+dx)
__device__ float g_wt[NTAPS * WTILE];

// --------------------------------------------------------------------------
// Repack weight [Cout, 27, Cin] -> [27, Cin, Cout]
// --------------------------------------------------------------------------
__global__ void transpose_w_kernel(const float* __restrict__ w) {
    int idx = blockIdx.x * blockDim.x + threadIdx.x;
    if (idx < NTAPS * WTILE) {
        int co = idx & (COUT - 1);
        int ci = (idx >> 6) & (CIN - 1);
        int t  = idx >> 12;
        // weight[co][t][ci] with t = flattened (kz,ky,kx)
        g_wt[idx] = w[(co * NTAPS + t) * CIN + ci];
    }
}

// --------------------------------------------------------------------------
// Center tap + bias: one warp per voxel.
// out[n, :] = bias + sp[n, :] @ Wc
// --------------------------------------------------------------------------
__global__ void center_kernel(const float* __restrict__ sp,
                              const float* __restrict__ bias,
                              float* __restrict__ out, int n_vox) {
    __shared__ float ws[WTILE];
    for (int i = threadIdx.x; i < WTILE; i += blockDim.x)
        ws[i] = g_wt[13 * WTILE + i];   // tap 13 = center (1,1,1)
    __syncthreads();

    const int lane = threadIdx.x & 31;
    const int warps_per_block = blockDim.x >> 5;
    const int warp = blockIdx.x * warps_per_block + (threadIdx.x >> 5);
    if (warp >= n_vox) return;

    const float* srow = sp + (long)warp * CIN;
    float s0 = srow[lane];
    float s1 = srow[lane + 32];
    float acc0 = bias[lane];
    float acc1 = bias[lane + 32];

#pragma unroll
    for (int ci = 0; ci < 32; ci++) {
        float sv = __shfl_sync(0xffffffffu, s0, ci);
        acc0 = fmaf(sv, ws[ci * COUT + lane], acc0);
        acc1 = fmaf(sv, ws[ci * COUT + lane + 32], acc1);
    }
#pragma unroll
    for (int ci = 0; ci < 32; ci++) {
        float sv = __shfl_sync(0xffffffffu, s1, ci);
        acc0 = fmaf(sv, ws[(ci + 32) * COUT + lane], acc0);
        acc1 = fmaf(sv, ws[(ci + 32) * COUT + lane + 32], acc1);
    }

    out[(long)warp * COUT + lane]      = acc0;
    out[(long)warp * COUT + lane + 32] = acc1;
}

// --------------------------------------------------------------------------
// Neighbor scatter: blockIdx.y = offset o (0..25), blocks along x grid-stride
// over the valid pairs of that offset. Weight tile for the offset's tap is
// pinned in smem. One warp per pair; 64 atomic adds per pair.
// --------------------------------------------------------------------------
__global__ void scatter_kernel(const float* __restrict__ sp,
                               const int* __restrict__ nei,
                               const int* __restrict__ sizes,
                               float* __restrict__ out, int P) {
    const int o = blockIdx.y;
    const int t = (o < 13) ? o : o + 1;   // skip center tap

    __shared__ float ws[WTILE];
    for (int i = threadIdx.x; i < WTILE; i += blockDim.x)
        ws[i] = g_wt[t * WTILE + i];
    __syncthreads();

    const int size = sizes[o];
    const int lane = threadIdx.x & 31;
    const int wid  = threadIdx.x >> 5;
    const int warps_per_block = blockDim.x >> 5;
    const long base = (long)o * P;

    for (int p = blockIdx.x * warps_per_block + wid; p < size;
         p += gridDim.x * warps_per_block) {
        const int out_idx = nei[(base + p) * 2 + 0];
        const int in_idx  = nei[(base + p) * 2 + 1];

        const float* srow = sp + (long)in_idx * CIN;
        float s0 = srow[lane];
        float s1 = srow[lane + 32];
        float acc0 = 0.f, acc1 = 0.f;

#pragma unroll
        for (int ci = 0; ci < 32; ci++) {
            float sv = __shfl_sync(0xffffffffu, s0, ci);
            acc0 = fmaf(sv, ws[ci * COUT + lane], acc0);
            acc1 = fmaf(sv, ws[ci * COUT + lane + 32], acc1);
        }
#pragma unroll
        for (int ci = 0; ci < 32; ci++) {
            float sv = __shfl_sync(0xffffffffu, s1, ci);
            acc0 = fmaf(sv, ws[(ci + 32) * COUT + lane], acc0);
            acc1 = fmaf(sv, ws[(ci + 32) * COUT + lane + 32], acc1);
        }

        float* orow = out + (long)out_idx * COUT;
        atomicAdd(&orow[lane],      acc0);
        atomicAdd(&orow[lane + 32], acc1);
    }
}

// --------------------------------------------------------------------------
extern "C" void kernel_launch(void* const* d_in, const int* in_sizes, int n_in,
                              void* d_out, int out_size) {
    const float* sp     = (const float*)d_in[0];   // [N, 64]
    const float* weight = (const float*)d_in[1];   // [64, 3,3,3, 64]
    const float* bias   = (const float*)d_in[2];   // [64]
    const int*   nei    = (const int*)d_in[3];     // [26, P, 2]
    const int*   sizes  = (const int*)d_in[4];     // [26]
    float* out = (float*)d_out;

    const int n_vox = in_sizes[0] / CIN;
    const int P     = in_sizes[3] / (NOFFS * 2);

    // 1) repack weights
    {
        int total = NTAPS * WTILE;
        transpose_w_kernel<<<(total + 255) / 256, 256>>>(weight);
    }

    // 2) center tap + bias (initializes every output row)
    {
        const int threads = 256;                  // 8 warps
        const int warps_per_block = threads / 32;
        int blocks = (n_vox + warps_per_block - 1) / warps_per_block;
        center_kernel<<<blocks, threads>>>(sp, bias, out, n_vox);
    }

    // 3) neighbor scatter with atomics
    {
        const int threads = 256;                  // 8 warps
        dim3 grid(32, NOFFS, 1);                  // 832 blocks total
        scatter_kernel<<<grid, threads>>>(sp, nei, sizes, out, P);
    }
}

// round 2
// speedup vs baseline: 1.9013x; 1.9013x over previous
#include <cuda_runtime.h>
#include <cuda_bf16.h>

#define CIN 64
#define COUT 64
#define NOFFS 26
#define NTAPS 27
#define WTILE (CIN * COUT)   // 4096 floats = 16 KB
#define PAIRS 4              // register blocking: pairs per warp iteration

// Transposed weights: wt[t][ci][co], t in 0..26 (tap index dz*9+dy*3+dx)
__device__ float g_wt[NTAPS * WTILE];

// --------------------------------------------------------------------------
// Repack weight [Cout, 27, Cin] -> [27, Cin, Cout]
// --------------------------------------------------------------------------
__global__ void transpose_w_kernel(const float* __restrict__ w) {
    int idx = blockIdx.x * blockDim.x + threadIdx.x;
    if (idx < NTAPS * WTILE) {
        int co = idx & (COUT - 1);
        int ci = (idx >> 6) & (CIN - 1);
        int t  = idx >> 12;
        g_wt[idx] = w[(co * NTAPS + t) * CIN + ci];
    }
}

// --------------------------------------------------------------------------
// Center tap + bias: one warp per 4 voxels, lane owns co = 2*lane, 2*lane+1.
// out[n, :] = bias + sp[n, :] @ Wc   (initializes every output row)
// --------------------------------------------------------------------------
__global__ void center_kernel(const float* __restrict__ sp,
                              const float* __restrict__ bias,
                              float* __restrict__ out, int n_vox) {
    __shared__ float ws[WTILE];
    for (int i = threadIdx.x; i < WTILE; i += blockDim.x)
        ws[i] = g_wt[13 * WTILE + i];   // tap 13 = center (1,1,1)
    __syncthreads();

    const int lane = threadIdx.x & 31;
    const int warps_per_block = blockDim.x >> 5;
    const int group = blockIdx.x * warps_per_block + (threadIdx.x >> 5);

    const int base_v = group * PAIRS;
    if (base_v >= n_vox) return;

    const float b0 = bias[2 * lane];
    const float b1 = bias[2 * lane + 1];

    float s0[PAIRS], s1[PAIRS];
    float acc0[PAIRS], acc1[PAIRS];
    int   vidx[PAIRS];
    bool  valid[PAIRS];

#pragma unroll
    for (int k = 0; k < PAIRS; k++) {
        int v = base_v + k;
        valid[k] = (v < n_vox);
        vidx[k]  = valid[k] ? v : (n_vox - 1);
        const float* srow = sp + (long)vidx[k] * CIN;
        s0[k] = __ldg(&srow[lane]);
        s1[k] = __ldg(&srow[lane + 32]);
        acc0[k] = b0;
        acc1[k] = b1;
    }

#pragma unroll
    for (int ci = 0; ci < 32; ci++) {
        float2 w2 = *(const float2*)&ws[ci * COUT + 2 * lane];
#pragma unroll
        for (int k = 0; k < PAIRS; k++) {
            float sv = __shfl_sync(0xffffffffu, s0[k], ci);
            acc0[k] = fmaf(sv, w2.x, acc0[k]);
            acc1[k] = fmaf(sv, w2.y, acc1[k]);
        }
    }
#pragma unroll
    for (int ci = 0; ci < 32; ci++) {
        float2 w2 = *(const float2*)&ws[(ci + 32) * COUT + 2 * lane];
#pragma unroll
        for (int k = 0; k < PAIRS; k++) {
            float sv = __shfl_sync(0xffffffffu, s1[k], ci);
            acc0[k] = fmaf(sv, w2.x, acc0[k]);
            acc1[k] = fmaf(sv, w2.y, acc1[k]);
        }
    }

#pragma unroll
    for (int k = 0; k < PAIRS; k++) {
        if (valid[k]) {
            float* orow = out + (long)vidx[k] * COUT;
            float2 r; r.x = acc0[k]; r.y = acc1[k];
            *(float2*)&orow[2 * lane] = r;
        }
    }
}

// --------------------------------------------------------------------------
// Neighbor scatter: blockIdx.y = offset o (0..25); warps grid-stride over
// groups of 4 pairs. Weight tile for the offset's tap pinned in smem,
// read as float2 once per 4 pairs. 64 atomic adds per pair.
// --------------------------------------------------------------------------
__global__ void scatter_kernel(const float* __restrict__ sp,
                               const int* __restrict__ nei,
                               const int* __restrict__ sizes,
                               float* __restrict__ out, int P) {
    const int o = blockIdx.y;
    const int t = (o < 13) ? o : o + 1;   // skip center tap

    __shared__ float ws[WTILE];
    for (int i = threadIdx.x; i < WTILE; i += blockDim.x)
        ws[i] = g_wt[t * WTILE + i];
    __syncthreads();

    const int size = sizes[o];
    if (size == 0) return;
    const int ngroups = (size + PAIRS - 1) / PAIRS;

    const int lane = threadIdx.x & 31;
    const int wid  = threadIdx.x >> 5;
    const int warps_per_block = blockDim.x >> 5;
    const long base = (long)o * P;

    for (int g = blockIdx.x * warps_per_block + wid; g < ngroups;
         g += gridDim.x * warps_per_block) {
        const int base_p = g * PAIRS;

        int   out_i[PAIRS];
        float s0[PAIRS], s1[PAIRS];
        float acc0[PAIRS], acc1[PAIRS];
        bool  valid[PAIRS];

#pragma unroll
        for (int k = 0; k < PAIRS; k++) {
            int p = base_p + k;
            valid[k] = (p < size);
            int pc = valid[k] ? p : (size - 1);
            out_i[k]   = __ldg(&nei[(base + pc) * 2 + 0]);
            int in_i   = __ldg(&nei[(base + pc) * 2 + 1]);
            const float* srow = sp + (long)in_i * CIN;
            s0[k] = __ldg(&srow[lane]);
            s1[k] = __ldg(&srow[lane + 32]);
            acc0[k] = 0.f;
            acc1[k] = 0.f;
        }

#pragma unroll
        for (int ci = 0; ci < 32; ci++) {
            float2 w2 = *(const float2*)&ws[ci * COUT + 2 * lane];
#pragma unroll
            for (int k = 0; k < PAIRS; k++) {
                float sv = __shfl_sync(0xffffffffu, s0[k], ci);
                acc0[k] = fmaf(sv, w2.x, acc0[k]);
                acc1[k] = fmaf(sv, w2.y, acc1[k]);
            }
        }
#pragma unroll
        for (int ci = 0; ci < 32; ci++) {
            float2 w2 = *(const float2*)&ws[(ci + 32) * COUT + 2 * lane];
#pragma unroll
            for (int k = 0; k < PAIRS; k++) {
                float sv = __shfl_sync(0xffffffffu, s1[k], ci);
                acc0[k] = fmaf(sv, w2.x, acc0[k]);
                acc1[k] = fmaf(sv, w2.y, acc1[k]);
            }
        }

#pragma unroll
        for (int k = 0; k < PAIRS; k++) {
            if (valid[k]) {
                float* orow = out + (long)out_i[k] * COUT;
                atomicAdd(&orow[2 * lane],     acc0[k]);
                atomicAdd(&orow[2 * lane + 1], acc1[k]);
            }
        }
    }
}

// --------------------------------------------------------------------------
extern "C" void kernel_launch(void* const* d_in, const int* in_sizes, int n_in,
                              void* d_out, int out_size) {
    const float* sp     = (const float*)d_in[0];   // [N, 64]
    const float* weight = (const float*)d_in[1];   // [64, 3,3,3, 64]
    const float* bias   = (const float*)d_in[2];   // [64]
    const int*   nei    = (const int*)d_in[3];     // [26, P, 2]
    const int*   sizes  = (const int*)d_in[4];     // [26]
    float* out = (float*)d_out;

    const int n_vox = in_sizes[0] / CIN;
    const int P     = in_sizes[3] / (NOFFS * 2);

    // 1) repack weights
    {
        int total = NTAPS * WTILE;
        transpose_w_kernel<<<(total + 255) / 256, 256>>>(weight);
    }

    // 2) center tap + bias (initializes every output row)
    {
        const int threads = 256;                  // 8 warps
        const int warps_per_block = threads / 32;
        int groups = (n_vox + PAIRS - 1) / PAIRS;
        int blocks = (groups + warps_per_block - 1) / warps_per_block;
        center_kernel<<<blocks, threads>>>(sp, bias, out, n_vox);
    }

    // 3) neighbor scatter with atomics
    {
        const int threads = 256;                  // 8 warps
        dim3 grid(48, NOFFS, 1);
        scatter_kernel<<<grid, threads>>>(sp, nei, sizes, out, P);
    }
}

// round 3
// speedup vs baseline: 2.0144x; 1.0595x over previous
#include <cuda_runtime.h>
#include <cuda_bf16.h>

#define CIN 64
#define COUT 64
#define NOFFS 26
#define NTAPS 27
#define CSLICES 26                 // center work split into 26 balanced slices
#define YTOT (NOFFS + CSLICES)     // 52
#define PAIRS 8                    // pairs per warp iteration
#define WSTRIDE 66                 // padded smem row stride (floats)
#define THREADS 256
#define WPB (THREADS / 32)

// ---- packed f32x2 helpers (FFMA2 only reachable via PTX) -------------------
__device__ __forceinline__ unsigned long long splat2(float s) {
    unsigned long long r;
    asm("mov.b64 %0, {%1, %1};" : "=l"(r) : "f"(s));
    return r;
}
__device__ __forceinline__ unsigned long long ffma2(unsigned long long a,
                                                    unsigned long long b,
                                                    unsigned long long c) {
    unsigned long long d;
    asm("fma.rn.f32x2 %0, %1, %2, %3;" : "=l"(d) : "l"(a), "l"(b), "l"(c));
    return d;
}

// ----------------------------------------------------------------------------
// One fused kernel. blockIdx.y:
//   0..25   -> neighbor-offset scatter (tap skips center), acc starts at 0
//   26..51  -> center slices (tap 13), acc starts at bias
// All contributions atomicAdd(float2) onto a pre-zeroed output.
// Each block transposes its tap's 64x64 weight tile into padded smem.
// ----------------------------------------------------------------------------
__global__ __launch_bounds__(THREADS, 2)
void conv_kernel(const float* __restrict__ sp,
                 const float* __restrict__ weight,
                 const float* __restrict__ bias,
                 const int2* __restrict__ nei,
                 const int* __restrict__ sizes,
                 float* __restrict__ out,
                 int P, int n_vox, int chunk) {
    __shared__ float ws[CIN * WSTRIDE];

    const int o = blockIdx.y;
    const bool is_center = (o >= NOFFS);
    const int t = is_center ? 13 : (o < 13 ? o : o + 1);

    // transpose weight[co][t][ci] -> ws[ci*WSTRIDE + co]
    // read coalesced over ci; write has only 2-way bank conflict (stride 66)
    for (int idx = threadIdx.x; idx < CIN * COUT; idx += THREADS) {
        int ci = idx & (CIN - 1);
        int co = idx >> 6;
        ws[ci * WSTRIDE + co] = weight[(co * NTAPS + t) * CIN + ci];
    }
    __syncthreads();

    int size, start = 0;
    long pair_base = 0;
    if (is_center) {
        start = (o - NOFFS) * chunk;
        size = n_vox - start;
        if (size > chunk) size = chunk;
        if (size <= 0) return;
    } else {
        size = sizes[o];
        if (size <= 0) return;
        pair_base = (long)o * P;
    }

    const int lane = threadIdx.x & 31;
    const int wid  = threadIdx.x >> 5;

    unsigned long long init_acc = 0ull;
    if (is_center) {
        float2 b = *(const float2*)&bias[2 * lane];
        asm("mov.b64 %0, {%1, %2};" : "=l"(init_acc) : "f"(b.x), "f"(b.y));
    }

    const int ngroups = (size + PAIRS - 1) / PAIRS;

    for (int g = blockIdx.x * WPB + wid; g < ngroups; g += gridDim.x * WPB) {
        const int base_p = g * PAIRS;

        const float4* srow[PAIRS];
        int  out_i[PAIRS];
        bool valid[PAIRS];
        unsigned long long acc[PAIRS];

#pragma unroll
        for (int k = 0; k < PAIRS; k++) {
            int p = base_p + k;
            valid[k] = (p < size);
            int pc = valid[k] ? p : (size - 1);
            int oi, ii;
            if (is_center) {
                oi = ii = start + pc;
            } else {
                int2 pr = __ldg(&nei[pair_base + pc]);
                oi = pr.x; ii = pr.y;
            }
            out_i[k] = oi;
            srow[k]  = (const float4*)(sp + (long)ii * CIN);
            acc[k]   = init_acc;
        }

#pragma unroll
        for (int c4 = 0; c4 < CIN / 4; c4++) {
            float4 sv[PAIRS];
#pragma unroll
            for (int k = 0; k < PAIRS; k++)
                sv[k] = __ldg(srow[k] + c4);   // uniform address -> broadcast

#pragma unroll
            for (int j = 0; j < 4; j++) {
                const int ci = c4 * 4 + j;
                unsigned long long w2 =
                    *(const unsigned long long*)&ws[ci * WSTRIDE + 2 * lane];
#pragma unroll
                for (int k = 0; k < PAIRS; k++) {
                    float s = (j == 0) ? sv[k].x
                            : (j == 1) ? sv[k].y
                            : (j == 2) ? sv[k].z
                                       : sv[k].w;
                    acc[k] = ffma2(splat2(s), w2, acc[k]);
                }
            }
        }

#pragma unroll
        for (int k = 0; k < PAIRS; k++) {
            if (valid[k]) {
                float2 v;
                asm("mov.b64 {%0, %1}, %2;" : "=f"(v.x), "=f"(v.y) : "l"(acc[k]));
                atomicAdd((float2*)(out + (long)out_i[k] * COUT) + lane, v);
            }
        }
    }
}

// ----------------------------------------------------------------------------
extern "C" void kernel_launch(void* const* d_in, const int* in_sizes, int n_in,
                              void* d_out, int out_size) {
    const float* sp     = (const float*)d_in[0];   // [N, 64]
    const float* weight = (const float*)d_in[1];   // [64, 3,3,3, 64]
    const float* bias   = (const float*)d_in[2];   // [64]
    const int2*  nei    = (const int2*)d_in[3];    // [26, P, 2] -> int2 pairs
    const int*   sizes  = (const int*)d_in[4];     // [26]
    float* out = (float*)d_out;

    const int n_vox = in_sizes[0] / CIN;
    const int P     = in_sizes[3] / (NOFFS * 2);
    const int chunk = (n_vox + CSLICES - 1) / CSLICES;

    // zero output (atomics accumulate onto it; bias added by center slices)
    cudaMemsetAsync(out, 0, (size_t)out_size * sizeof(float), 0);

    dim3 grid(24, YTOT, 1);
    conv_kernel<<<grid, THREADS>>>(sp, weight, bias, nei, sizes, out,
                                   P, n_vox, chunk);
}

// round 4
// speedup vs baseline: 2.7615x; 1.3708x over previous
#include <cuda_runtime.h>
#include <cuda_bf16.h>

#define CIN 64
#define COUT 64
#define NOFFS 26
#define NTAPS 27
#define CSLICES 26                 // center work split into 26 balanced slices
#define YTOT (NOFFS + CSLICES)     // 52
#define THREADS 256
#define WPB (THREADS / 32)         // 8 warps per block
#define GP 8                       // pairs per warp-group (4 per half-warp)
#define SROW 68                    // padded row stride in floats (16B-aligned)

typedef unsigned long long u64;

// ---- packed f32x2 helpers (FFMA2 only reachable via PTX) -------------------
__device__ __forceinline__ u64 splat2(float s) {
    u64 r;
    asm("mov.b64 %0, {%1, %1};" : "=l"(r) : "f"(s));
    return r;
}
__device__ __forceinline__ u64 pack2(float a, float b) {
    u64 r;
    asm("mov.b64 %0, {%1, %2};" : "=l"(r) : "f"(a), "f"(b));
    return r;
}
__device__ __forceinline__ u64 ffma2(u64 a, u64 b, u64 c) {
    u64 d;
    asm("fma.rn.f32x2 %0, %1, %2, %3;" : "=l"(d) : "l"(a), "l"(b), "l"(c));
    return d;
}
__device__ __forceinline__ float2 unpack2(u64 v) {
    float2 r;
    asm("mov.b64 {%0, %1}, %2;" : "=f"(r.x), "=f"(r.y) : "l"(v));
    return r;
}

// ----------------------------------------------------------------------------
// Fused kernel. blockIdx.y:
//   0..25  -> neighbor-offset scatter (tap != center), acc starts at 0
//   26..51 -> center slices (tap 13), acc starts at bias
// Lane layout: h = lane>>4 (half-warp), q = lane&15 -> lane owns co 4q..4q+3.
// Half h processes pairs (group*8 + 4h + k), k=0..3.
// ----------------------------------------------------------------------------
__global__ __launch_bounds__(THREADS, 3)
void conv_kernel(const float* __restrict__ sp,
                 const float* __restrict__ weight,
                 const float* __restrict__ bias,
                 const int2* __restrict__ nei,
                 const int* __restrict__ sizes,
                 float* __restrict__ out,
                 int P, int n_vox, int chunk) {
    __shared__ __align__(16) float ws[CIN * SROW];          // 17408 B
    __shared__ __align__(16) float srows[WPB][GP][SROW];    // 17408 B

    const int o = blockIdx.y;
    const bool is_center = (o >= NOFFS);
    const int t = is_center ? 13 : (o < 13 ? o : o + 1);

    // transpose weight[co][t][ci] -> ws[ci*SROW + co]
    for (int idx = threadIdx.x; idx < CIN * COUT; idx += THREADS) {
        int ci = idx & (CIN - 1);
        int co = idx >> 6;
        ws[ci * SROW + co] = weight[(co * NTAPS + t) * CIN + ci];
    }
    __syncthreads();

    int size, start = 0;
    long pair_base = 0;
    if (is_center) {
        start = (o - NOFFS) * chunk;
        size = n_vox - start;
        if (size > chunk) size = chunk;
        if (size <= 0) return;
    } else {
        size = sizes[o];
        if (size <= 0) return;
        pair_base = (long)o * P;
    }

    const int lane = threadIdx.x & 31;
    const int wid  = threadIdx.x >> 5;
    const int h    = lane >> 4;    // half-warp
    const int q    = lane & 15;    // co base = 4*q

    // per-lane accumulator init (center gets bias for its co quad)
    u64 init0 = 0ull, init1 = 0ull;
    if (is_center) {
        float4 b4 = __ldg((const float4*)bias + q);
        init0 = pack2(b4.x, b4.y);
        init1 = pack2(b4.z, b4.w);
    }

    const int ngroups = (size + GP - 1) / GP;

    for (int g = blockIdx.x * WPB + wid; g < ngroups; g += gridDim.x * WPB) {
        const int base_p = g * GP;

        // lanes 0..7 fetch (out,in) for pairs base_p+lane (clamped)
        int oi_r = 0, ii_r = 0;
        if (lane < GP) {
            int p = base_p + lane;
            if (p >= size) p = size - 1;
            if (is_center) {
                oi_r = ii_r = start + p;
            } else {
                int2 pr = __ldg(&nei[pair_base + p]);
                oi_r = pr.x;
                ii_r = pr.y;
            }
        }
        __syncwarp();

        // stage 8 rows (256B each) coalesced: instr i covers rows 2i, 2i+1
#pragma unroll
        for (int i = 0; i < 4; i++) {
            int row = 2 * i + h;
            int ii  = __shfl_sync(0xffffffffu, ii_r, row);
            float4 v = __ldg((const float4*)(sp + (long)ii * CIN) + q);
            *(float4*)&srows[wid][row][q * 4] = v;
        }
        __syncwarp();

        u64 acc[4][2];
#pragma unroll
        for (int k = 0; k < 4; k++) { acc[k][0] = init0; acc[k][1] = init1; }

#pragma unroll
        for (int c4 = 0; c4 < CIN / 4; c4++) {
            float4 sv[4];
#pragma unroll
            for (int k = 0; k < 4; k++)
                sv[k] = *(const float4*)&srows[wid][4 * h + k][c4 * 4];

#pragma unroll
            for (int j = 0; j < 4; j++) {
                const int ci = c4 * 4 + j;
                ulonglong2 w2 = *(const ulonglong2*)&ws[ci * SROW + 4 * q];
#pragma unroll
                for (int k = 0; k < 4; k++) {
                    float s = (j == 0) ? sv[k].x
                            : (j == 1) ? sv[k].y
                            : (j == 2) ? sv[k].z
                                       : sv[k].w;
                    u64 s2 = splat2(s);
                    acc[k][0] = ffma2(s2, w2.x, acc[k][0]);
                    acc[k][1] = ffma2(s2, w2.y, acc[k][1]);
                }
            }
        }

        // epilogue: half h scatters its 4 pairs; lane covers co 4q..4q+3
#pragma unroll
        for (int k = 0; k < 4; k++) {
            int oi = __shfl_sync(0xffffffffu, oi_r, 4 * h + k);
            if (base_p + 4 * h + k < size) {
                float2* orow = (float2*)(out + (long)oi * COUT);
                atomicAdd(orow + 2 * q,     unpack2(acc[k][0]));
                atomicAdd(orow + 2 * q + 1, unpack2(acc[k][1]));
            }
        }
    }
}

// ----------------------------------------------------------------------------
extern "C" void kernel_launch(void* const* d_in, const int* in_sizes, int n_in,
                              void* d_out, int out_size) {
    const float* sp     = (const float*)d_in[0];   // [N, 64]
    const float* weight = (const float*)d_in[1];   // [64, 3,3,3, 64]
    const float* bias   = (const float*)d_in[2];   // [64]
    const int2*  nei    = (const int2*)d_in[3];    // [26, P, 2] -> int2 pairs
    const int*   sizes  = (const int*)d_in[4];     // [26]
    float* out = (float*)d_out;

    const int n_vox = in_sizes[0] / CIN;
    const int P     = in_sizes[3] / (NOFFS * 2);
    const int chunk = (n_vox + CSLICES - 1) / CSLICES;

    // zero output (atomics accumulate onto it; bias added by center slices)
    cudaMemsetAsync(out, 0, (size_t)out_size * sizeof(float), 0);

    dim3 grid(24, YTOT, 1);
    conv_kernel<<<grid, THREADS>>>(sp, weight, bias, nei, sizes, out,
                                   P, n_vox, chunk);
}